// round 5
// baseline (speedup 1.0000x reference)
#include <cuda_runtime.h>
#include <cuda_bf16.h>
#include <cstdint>

#define D    128
#define HS   128
#define MAXV 1000064
#define MAXG 16384
#define AP   136      // padded smem row pitch in bf16 elems
#define TILE 128      // rows per tile
#define NSM  148
#define NTHR 384      // 8 consumer warps + 4 producer warps

// ---------------- device scratch ----------------
__device__ float g_e[MAXV];
__device__ int   g_starts[MAXG + 1];
__device__ __align__(16) __nv_bfloat16 g_Whi[HS * D];
__device__ __align__(16) __nv_bfloat16 g_Wlo[HS * D];

// ---------------- smem layout (bytes) ----------------
#define SM_SB    0                       // 128 f32 bias
#define SM_SW    512                     // 128 f32 w_score
#define SM_SE    1024                    // 2 x 128 f32 = 1024
#define SM_BHI   2048                    // 128 x AP bf16 = 34816
#define SM_BLO   (SM_BHI + 34816)        // 36864
#define SM_A0HI  (SM_BLO + 34816)        // 71680
#define SM_A0LO  (SM_A0HI + 34816)       // 106496
#define SM_A1HI  (SM_A0LO + 34816)       // 141312
#define SM_A1LO  (SM_A1HI + 34816)       // 176128
#define SMEM1_TOTAL (SM_A1LO + 34816)    // 210944

// ---------------- helpers ----------------
__device__ __forceinline__ unsigned su32(const void* p) {
    return (unsigned)__cvta_generic_to_shared(p);
}
__device__ __forceinline__ unsigned pk(__nv_bfloat16 a, __nv_bfloat16 b) {
    unsigned short ua = *(unsigned short*)&a, ub = *(unsigned short*)&b;
    return (unsigned)ua | ((unsigned)ub << 16);
}
__device__ __forceinline__ float tanh_approx(float x) {
    float y;
    asm("tanh.approx.f32 %0, %1;" : "=f"(y) : "f"(x));
    return y;
}

#define LDSM4(r0, r1, r2, r3, addr)                                          \
    asm volatile("ldmatrix.sync.aligned.m8n8.x4.shared.b16 {%0,%1,%2,%3}, [%4];" \
                 : "=r"(r0), "=r"(r1), "=r"(r2), "=r"(r3) : "r"(addr))

#define MMA16816(c, a0, a1, a2, a3, b0, b1)                                  \
    asm volatile(                                                            \
        "mma.sync.aligned.m16n8k16.row.col.f32.bf16.bf16.f32 "               \
        "{%0,%1,%2,%3},{%4,%5,%6,%7},{%8,%9},{%0,%1,%2,%3};"                 \
        : "+f"(c[0]), "+f"(c[1]), "+f"(c[2]), "+f"(c[3])                     \
        : "r"(a0), "r"(a1), "r"(a2), "r"(a3), "r"(b0), "r"(b1))

// ---------------- small kernels ----------------
__global__ void k_prep_w(const float* __restrict__ W) {
    int i = blockIdx.x * 256 + threadIdx.x;
    if (i < HS * D) {
        float x = W[i];
        __nv_bfloat16 h = __float2bfloat16(x);
        g_Whi[i] = h;
        g_Wlo[i] = __float2bfloat16(x - __bfloat162float(h));
    }
}

__global__ void k_bounds(const void* __restrict__ batch_raw, int V, int G) {
    int i = blockIdx.x * 256 + threadIdx.x;
    if (i >= V) return;
    bool is64 =
        (((const unsigned long long*)batch_raw)[V / 2 - 1] < (1ULL << 31));
    auto bat = [&](int j) -> int {
        return is64 ? (int)((const long long*)batch_raw)[j]
                    : ((const int*)batch_raw)[j];
    };
    int cur = bat(i);
    int prev = (i == 0) ? -1 : bat(i - 1);
    for (int g = prev + 1; g <= cur && g <= G; ++g) g_starts[g] = i;
    if (i == V - 1)
        for (int g = cur + 1; g <= G; ++g) g_starts[g] = V;
}

// ---------------- K1 staging: TILE x 128 fp32 -> bf16 hi/lo ----------------
__device__ __forceinline__ void stage_tile(char* smem, const float* __restrict__ H,
                                           long tile, int buf, int V,
                                           int tpart, int npart) {
    __nv_bfloat16* dhi = (__nv_bfloat16*)(smem + (buf ? SM_A1HI : SM_A0HI));
    __nv_bfloat16* dlo = (__nv_bfloat16*)(smem + (buf ? SM_A1LO : SM_A0LO));
    for (int idx = tpart; idx < TILE * 16; idx += npart) {
        int row = idx >> 4;
        int k8  = (idx & 15) << 3;
        long gr = tile * TILE + row;
        float4 v0 = make_float4(0.f, 0.f, 0.f, 0.f), v1 = v0;
        if (gr < (long)V) {
            const float4* p = (const float4*)(H + (size_t)gr * D + k8);
            v0 = p[0];
            v1 = p[1];
        }
        float f[8] = {v0.x, v0.y, v0.z, v0.w, v1.x, v1.y, v1.z, v1.w};
        unsigned hi[4], lo[4];
#pragma unroll
        for (int p2 = 0; p2 < 4; ++p2) {
            __nv_bfloat16 ha = __float2bfloat16(f[2 * p2]);
            __nv_bfloat16 hb = __float2bfloat16(f[2 * p2 + 1]);
            __nv_bfloat16 la = __float2bfloat16(f[2 * p2] - __bfloat162float(ha));
            __nv_bfloat16 lb = __float2bfloat16(f[2 * p2 + 1] - __bfloat162float(hb));
            hi[p2] = pk(ha, hb);
            lo[p2] = pk(la, lb);
        }
        int off = row * AP + k8;
        *(uint4*)(dhi + off) = make_uint4(hi[0], hi[1], hi[2], hi[3]);
        *(uint4*)(dlo + off) = make_uint4(lo[0], lo[1], lo[2], lo[3]);
    }
}

// ---------------- K1: persistent split-bf16 HMMA, 8 consumer warps --------
__global__ __launch_bounds__(NTHR, 1) void k1_tc(const float* __restrict__ H,
                                                 const float* __restrict__ bp,
                                                 const float* __restrict__ ws,
                                                 int V, int nTiles) {
    extern __shared__ __align__(16) char smem[];
    int tid = threadIdx.x, wid = tid >> 5, lane = tid & 31;
    float* sb = (float*)(smem + SM_SB);
    float* sw = (float*)(smem + SM_SW);
    float* se = (float*)(smem + SM_SE);   // [2][128]

    if (tid < 128) { sb[tid] = bp[tid]; sw[tid] = ws[tid]; }

    // stage stationary B = W hi/lo
    for (int idx = tid; idx < 128 * 16; idx += NTHR) {
        int row = idx >> 4;
        int k8  = (idx & 15) << 3;
        uint4 vh = *(const uint4*)(g_Whi + row * D + k8);
        uint4 vl = *(const uint4*)(g_Wlo + row * D + k8);
        int off = row * AP + k8;
        *(uint4*)((__nv_bfloat16*)(smem + SM_BHI) + off) = vh;
        *(uint4*)((__nv_bfloat16*)(smem + SM_BLO) + off) = vl;
    }

    int nt = 0;
    {
        int rem = nTiles - blockIdx.x;
        if (rem > 0) nt = (rem + (int)gridDim.x - 1) / (int)gridDim.x;
    }

    if (nt > 0)
        stage_tile((char*)smem, H, (long)blockIdx.x, 0, V, tid, NTHR);
    __syncthreads();

    // consumer geometry (warps 0-7): 4(M) x 2(N), warp tile 32 x 64
    int wm = wid >> 1, wn = wid & 1;
    int rb = wm * 32, cb = wn * 64;
    unsigned aoff = ((rb + (lane & 15)) * AP + ((lane >> 4) << 3)) * 2;
    unsigned boff =
        ((cb + (lane & 7) + ((lane >> 4) << 3)) * AP + (((lane >> 3) & 1) << 3)) * 2;
    unsigned bhi_s = su32(smem + SM_BHI) + boff;
    unsigned blo_s = su32(smem + SM_BLO) + boff;

    for (int j = 0; j < nt; ++j) {
        int b = j & 1, bn = (j + 1) & 1;
        long tj = (long)blockIdx.x + (long)j * gridDim.x;

        if (wid >= 8) {
            if (j + 1 < nt) {
                long tj1 = (long)blockIdx.x + (long)(j + 1) * gridDim.x;
                stage_tile((char*)smem, H, tj1, bn, V, tid - 256, 128);
            }
        } else {
            unsigned ahi_s = su32(smem + (b ? SM_A1HI : SM_A0HI)) + aoff;
            unsigned alo_s = su32(smem + (b ? SM_A1LO : SM_A0LO)) + aoff;

            float acc[2][8][4];
#pragma unroll
            for (int s = 0; s < 2; s++)
#pragma unroll
                for (int q = 0; q < 8; q++)
#pragma unroll
                    for (int c = 0; c < 4; c++) acc[s][q][c] = 0.f;

#pragma unroll
            for (int kk = 0; kk < 8; ++kk) {
                unsigned ah[2][4], bh[16];
#pragma unroll
                for (int s = 0; s < 2; ++s)
                    LDSM4(ah[s][0], ah[s][1], ah[s][2], ah[s][3],
                          ahi_s + kk * 32 + s * (16 * AP * 2));
#pragma unroll
                for (int p = 0; p < 4; ++p)
                    LDSM4(bh[4 * p], bh[4 * p + 1], bh[4 * p + 2], bh[4 * p + 3],
                          bhi_s + kk * 32 + p * (16 * AP * 2));
                // pass 0: Ahi * Bhi
#pragma unroll
                for (int s = 0; s < 2; ++s)
#pragma unroll
                    for (int q = 0; q < 8; ++q) {
                        int bi = (q >> 1) * 4 + ((q & 1) << 1);
                        MMA16816(acc[s][q], ah[s][0], ah[s][1], ah[s][2],
                                 ah[s][3], bh[bi], bh[bi + 1]);
                    }
                // pass 1: Ahi * Blo
                unsigned bl[16];
#pragma unroll
                for (int p = 0; p < 4; ++p)
                    LDSM4(bl[4 * p], bl[4 * p + 1], bl[4 * p + 2], bl[4 * p + 3],
                          blo_s + kk * 32 + p * (16 * AP * 2));
#pragma unroll
                for (int s = 0; s < 2; ++s)
#pragma unroll
                    for (int q = 0; q < 8; ++q) {
                        int bi = (q >> 1) * 4 + ((q & 1) << 1);
                        MMA16816(acc[s][q], ah[s][0], ah[s][1], ah[s][2],
                                 ah[s][3], bl[bi], bl[bi + 1]);
                    }
                // pass 2: Alo * Bhi
                unsigned al[2][4];
#pragma unroll
                for (int s = 0; s < 2; ++s)
                    LDSM4(al[s][0], al[s][1], al[s][2], al[s][3],
                          alo_s + kk * 32 + s * (16 * AP * 2));
#pragma unroll
                for (int s = 0; s < 2; ++s)
#pragma unroll
                    for (int q = 0; q < 8; ++q) {
                        int bi = (q >> 1) * 4 + ((q & 1) << 1);
                        MMA16816(acc[s][q], al[s][0], al[s][1], al[s][2],
                                 al[s][3], bh[bi], bh[bi + 1]);
                    }
            }

            // epilogue: tanh + dot with w
            float bv[16], wv[16];
#pragma unroll
            for (int q = 0; q < 8; ++q)
#pragma unroll
                for (int par = 0; par < 2; ++par) {
                    int col = cb + q * 8 + (lane & 3) * 2 + par;
                    bv[q * 2 + par] = sb[col];
                    wv[q * 2 + par] = sw[col];
                }
            float ps[4] = {0.f, 0.f, 0.f, 0.f};
#pragma unroll
            for (int s = 0; s < 2; ++s)
#pragma unroll
                for (int q = 0; q < 8; ++q)
#pragma unroll
                    for (int e = 0; e < 4; ++e) {
                        float z = acc[s][q][e] + bv[q * 2 + (e & 1)];
                        ps[s * 2 + (e >> 1)] += tanh_approx(z) * wv[q * 2 + (e & 1)];
                    }
#pragma unroll
            for (int q = 0; q < 4; ++q) {
                ps[q] += __shfl_xor_sync(0xffffffffu, ps[q], 1);
                ps[q] += __shfl_xor_sync(0xffffffffu, ps[q], 2);
            }
            if ((lane & 3) == 0) {
#pragma unroll
                for (int q = 0; q < 4; ++q) {
                    int r = rb + (q >> 1) * 16 + (lane >> 2) + (q & 1) * 8;
                    se[wn * 128 + r] = ps[q];   // disjoint per (wm,wn)
                }
            }
            asm volatile("bar.sync 1, 256;" ::: "memory");
            if (tid < 128) {
                long grow = tj * TILE + tid;
                if (grow < (long)V) g_e[grow] = se[tid] + se[128 + tid];
            }
        }
        __syncthreads();
    }
}

// ---------------- K23: fused segment softmax + pooling ----------------
__global__ __launch_bounds__(128) void k23_pool(const float* __restrict__ H,
                                                float* __restrict__ out) {
    __shared__ float se[1024];
    __shared__ float red[128];
    int g = blockIdx.x, tid = threadIdx.x;
    int s = g_starts[g], t = g_starts[g + 1];
    int len = t - s;
    bool small = (len <= 1024);

    float m = -1e30f;
    if (small) {
        for (int i = tid; i < len; i += 128) {
            float e = g_e[s + i];
            se[i] = e;
            m = fmaxf(m, e);
        }
    } else {
        for (int i = tid; i < len; i += 128) m = fmaxf(m, g_e[s + i]);
    }
    red[tid] = m;
    __syncthreads();
#pragma unroll
    for (int o = 64; o > 0; o >>= 1) {
        if (tid < o) red[tid] = fmaxf(red[tid], red[tid + o]);
        __syncthreads();
    }
    m = red[0];
    __syncthreads();

    float sum = 0.f;
    if (small) {
        for (int i = tid; i < len; i += 128) {
            float a = __expf(se[i] - m);
            se[i] = a;
            sum += a;
        }
    } else {
        for (int i = tid; i < len; i += 128) sum += __expf(g_e[s + i] - m);
    }
    red[tid] = sum;
    __syncthreads();
#pragma unroll
    for (int o = 64; o > 0; o >>= 1) {
        if (tid < o) red[tid] += red[tid + o];
        __syncthreads();
    }
    float inv = 1.0f / fmaxf(red[0], 1e-12f);
    __syncthreads();

    int d = tid;
    float a0 = 0.f, a1 = 0.f, a2 = 0.f, a3 = 0.f;
    if (small) {
        int i = 0;
        for (; i + 3 < len; i += 4) {
            a0 += se[i]     * H[(size_t)(s + i)     * D + d];
            a1 += se[i + 1] * H[(size_t)(s + i + 1) * D + d];
            a2 += se[i + 2] * H[(size_t)(s + i + 2) * D + d];
            a3 += se[i + 3] * H[(size_t)(s + i + 3) * D + d];
        }
        for (; i < len; ++i) a0 += se[i] * H[(size_t)(s + i) * D + d];
    } else {
        for (int i = 0; i < len; ++i)
            a0 += __expf(g_e[s + i] - m) * H[(size_t)(s + i) * D + d];
    }
    out[(size_t)g * D + d] = (a0 + a1 + a2 + a3) * inv;
}

// ---------------- launch ----------------
extern "C" void kernel_launch(void* const* d_in, const int* in_sizes, int n_in,
                              void* d_out, int out_size) {
    const float* H  = (const float*)d_in[0];
    const void*  bt = d_in[1];
    const float* Wp = (const float*)d_in[2];
    const float* bp = (const float*)d_in[3];
    const float* ws = (const float*)d_in[4];
    float* out = (float*)d_out;

    int V = in_sizes[1];
    int G = out_size / D;
    if (G > MAXG) G = MAXG;
    int nTiles = (V + TILE - 1) / TILE;

    cudaFuncSetAttribute(k1_tc, cudaFuncAttributeMaxDynamicSharedMemorySize,
                         SMEM1_TOTAL);

    k_prep_w<<<(HS * D + 255) / 256, 256>>>(Wp);
    k_bounds<<<(V + 255) / 256, 256>>>(bt, V, G);
    k1_tc<<<NSM, NTHR, SMEM1_TOTAL>>>(H, bp, ws, V, nTiles);
    k23_pool<<<G, 128>>>(H, out);
}

// round 6
// speedup vs baseline: 1.0314x; 1.0314x over previous
#include <cuda_runtime.h>
#include <cuda_fp16.h>
#include <cstdint>

#define D    128
#define HS   128
#define MAXG 16384
#define AP   136      // padded smem row pitch in fp16 elems
#define TILE 128      // rows per tile
#define NSM  148
#define NTHR 384      // 8 consumer warps + 4 producer warps

// ---------------- device scratch ----------------
__device__ float g_den[MAXG];
__device__ int   g_is64;
__device__ __align__(16) __half g_Wh[HS * D];

// ---------------- smem layout (bytes) ----------------
#define SM_SB    0                       // 128 f32 bias
#define SM_SW    512                     // 128 f32 w_score
#define SM_SE    1024                    // 2 x 128 f32
#define SM_POOL  2048                    // 128 f32 exp(e)
#define SM_BAT   2560                    // 128 int batch ids
#define SM_FLAG  3072                    // 128 int run-start flags
#define SM_BHI   3584                    // 128 x AP fp16 = 34816
#define SM_A0HI  (SM_BHI + 34816)        // 38400
#define SM_A0LO  (SM_A0HI + 34816)       // 73216
#define SM_A1HI  (SM_A0LO + 34816)       // 108032
#define SM_A1LO  (SM_A1HI + 34816)       // 142848
#define SMEM1_TOTAL (SM_A1LO + 34816)    // 177664

// ---------------- helpers ----------------
__device__ __forceinline__ unsigned su32(const void* p) {
    return (unsigned)__cvta_generic_to_shared(p);
}
__device__ __forceinline__ unsigned pkh(__half a, __half b) {
    unsigned short ua = *(unsigned short*)&a, ub = *(unsigned short*)&b;
    return (unsigned)ua | ((unsigned)ub << 16);
}
__device__ __forceinline__ float tanh_approx(float x) {
    float y;
    asm("tanh.approx.f32 %0, %1;" : "=f"(y) : "f"(x));
    return y;
}

#define LDSM4(r0, r1, r2, r3, addr)                                          \
    asm volatile("ldmatrix.sync.aligned.m8n8.x4.shared.b16 {%0,%1,%2,%3}, [%4];" \
                 : "=r"(r0), "=r"(r1), "=r"(r2), "=r"(r3) : "r"(addr))

#define MMA16816F(c, a0, a1, a2, a3, b0, b1)                                 \
    asm volatile(                                                            \
        "mma.sync.aligned.m16n8k16.row.col.f32.f16.f16.f32 "                 \
        "{%0,%1,%2,%3},{%4,%5,%6,%7},{%8,%9},{%0,%1,%2,%3};"                 \
        : "+f"(c[0]), "+f"(c[1]), "+f"(c[2]), "+f"(c[3])                     \
        : "r"(a0), "r"(a1), "r"(a2), "r"(a3), "r"(b0), "r"(b1))

// ---------------- K_prep: W -> fp16, zero den, batch dtype flag ----------
__global__ void k_prep(const float* __restrict__ W,
                       const void* __restrict__ bt, int V) {
    int i = blockIdx.x * 256 + threadIdx.x;
    if (i < HS * D) g_Wh[i] = __float2half_rn(W[i]);
    if (i < MAXG) g_den[i] = 0.f;
    if (i == 0)
        g_is64 = (((const unsigned long long*)bt)[V / 2 - 1] < (1ULL << 31)) ? 1 : 0;
}

__global__ void k_zero(float* __restrict__ out, int n) {
    int i = blockIdx.x * 256 + threadIdx.x;
    if (i < n) out[i] = 0.f;
}

// ---------------- K1 staging: TILE x 128 fp32 -> fp16 hi/lo ----------------
__device__ __forceinline__ void stage_tile(char* smem, const float* __restrict__ H,
                                           long tile, int buf, int V,
                                           int tpart, int npart) {
    __half* dhi = (__half*)(smem + (buf ? SM_A1HI : SM_A0HI));
    __half* dlo = (__half*)(smem + (buf ? SM_A1LO : SM_A0LO));
    for (int idx = tpart; idx < TILE * 16; idx += npart) {
        int row = idx >> 4;
        int k8  = (idx & 15) << 3;
        long gr = tile * TILE + row;
        float4 v0 = make_float4(0.f, 0.f, 0.f, 0.f), v1 = v0;
        if (gr < (long)V) {
            const float4* p = (const float4*)(H + (size_t)gr * D + k8);
            v0 = p[0];
            v1 = p[1];
        }
        float f[8] = {v0.x, v0.y, v0.z, v0.w, v1.x, v1.y, v1.z, v1.w};
        unsigned hi[4], lo[4];
#pragma unroll
        for (int p2 = 0; p2 < 4; ++p2) {
            __half ha = __float2half_rn(f[2 * p2]);
            __half hb = __float2half_rn(f[2 * p2 + 1]);
            __half la = __float2half_rn(f[2 * p2] - __half2float(ha));
            __half lb = __float2half_rn(f[2 * p2 + 1] - __half2float(hb));
            hi[p2] = pkh(ha, hb);
            lo[p2] = pkh(la, lb);
        }
        int off = row * AP + k8;
        *(uint4*)(dhi + off) = make_uint4(hi[0], hi[1], hi[2], hi[3]);
        *(uint4*)(dlo + off) = make_uint4(lo[0], lo[1], lo[2], lo[3]);
    }
}

// ---------------- K1: persistent 2-pass fp16 HMMA + fused softmax-pool ----
__global__ __launch_bounds__(NTHR, 1) void k1_tc(const float* __restrict__ H,
                                                 const void* __restrict__ bt,
                                                 const float* __restrict__ bp,
                                                 const float* __restrict__ ws,
                                                 float* __restrict__ num,
                                                 int V, int nTiles) {
    extern __shared__ __align__(16) char smem[];
    int tid = threadIdx.x, wid = tid >> 5, lane = tid & 31;
    float* sb    = (float*)(smem + SM_SB);
    float* sw    = (float*)(smem + SM_SW);
    float* se    = (float*)(smem + SM_SE);    // [2][128]
    float* spool = (float*)(smem + SM_POOL);  // [128]
    int*   sbat  = (int*)(smem + SM_BAT);     // [128]
    int*   sflag = (int*)(smem + SM_FLAG);    // [128]

    if (tid < 128) { sb[tid] = bp[tid]; sw[tid] = ws[tid]; }
    int is64 = g_is64;

    // stage stationary B = fp16(W)
    for (int idx = tid; idx < 128 * 16; idx += NTHR) {
        int row = idx >> 4;
        int k8  = (idx & 15) << 3;
        uint4 vh = *(const uint4*)(g_Wh + row * D + k8);
        *(uint4*)((__half*)(smem + SM_BHI) + row * AP + k8) = vh;
    }

    int nt = 0;
    {
        int rem = nTiles - blockIdx.x;
        if (rem > 0) nt = (rem + (int)gridDim.x - 1) / (int)gridDim.x;
    }

    if (nt > 0)
        stage_tile((char*)smem, H, (long)blockIdx.x, 0, V, tid, NTHR);
    __syncthreads();

    // consumer geometry (warps 0-7): 4(M) x 2(N), warp tile 32 x 64
    int wm = wid >> 1, wn = wid & 1;
    int rb = wm * 32, cb = wn * 64;
    unsigned aoff = ((rb + (lane & 15)) * AP + ((lane >> 4) << 3)) * 2;
    unsigned boff =
        ((cb + (lane & 7) + ((lane >> 4) << 3)) * AP + (((lane >> 3) & 1) << 3)) * 2;
    unsigned bhi_s = su32(smem + SM_BHI) + boff;

    for (int j = 0; j < nt; ++j) {
        int b = j & 1, bn = (j + 1) & 1;
        long tj = (long)blockIdx.x + (long)j * gridDim.x;

        if (wid >= 8) {
            // producers: stage next tile
            if (j + 1 < nt) {
                long tj1 = (long)blockIdx.x + (long)(j + 1) * gridDim.x;
                stage_tile((char*)smem, H, tj1, bn, V, tid - 256, 128);
            }
        } else {
            unsigned ahi_s = su32(smem + (b ? SM_A1HI : SM_A0HI)) + aoff;
            unsigned alo_s = su32(smem + (b ? SM_A1LO : SM_A0LO)) + aoff;

            float acc[2][8][4];
#pragma unroll
            for (int s = 0; s < 2; s++)
#pragma unroll
                for (int q = 0; q < 8; q++)
#pragma unroll
                    for (int c = 0; c < 4; c++) acc[s][q][c] = 0.f;

#pragma unroll
            for (int kk = 0; kk < 8; ++kk) {
                unsigned ah[2][4], bh[16];
#pragma unroll
                for (int s = 0; s < 2; ++s)
                    LDSM4(ah[s][0], ah[s][1], ah[s][2], ah[s][3],
                          ahi_s + kk * 32 + s * (16 * AP * 2));
#pragma unroll
                for (int p = 0; p < 4; ++p)
                    LDSM4(bh[4 * p], bh[4 * p + 1], bh[4 * p + 2], bh[4 * p + 3],
                          bhi_s + kk * 32 + p * (16 * AP * 2));
                // pass 0: Ahi * B
#pragma unroll
                for (int s = 0; s < 2; ++s)
#pragma unroll
                    for (int q = 0; q < 8; ++q) {
                        int bi = (q >> 1) * 4 + ((q & 1) << 1);
                        MMA16816F(acc[s][q], ah[s][0], ah[s][1], ah[s][2],
                                  ah[s][3], bh[bi], bh[bi + 1]);
                    }
                // pass 1: Alo * B
                unsigned al[2][4];
#pragma unroll
                for (int s = 0; s < 2; ++s)
                    LDSM4(al[s][0], al[s][1], al[s][2], al[s][3],
                          alo_s + kk * 32 + s * (16 * AP * 2));
#pragma unroll
                for (int s = 0; s < 2; ++s)
#pragma unroll
                    for (int q = 0; q < 8; ++q) {
                        int bi = (q >> 1) * 4 + ((q & 1) << 1);
                        MMA16816F(acc[s][q], al[s][0], al[s][1], al[s][2],
                                  al[s][3], bh[bi], bh[bi + 1]);
                    }
            }

            // epilogue part 1: tanh-dot -> se
            float bv[16], wv[16];
#pragma unroll
            for (int q = 0; q < 8; ++q)
#pragma unroll
                for (int par = 0; par < 2; ++par) {
                    int col = cb + q * 8 + (lane & 3) * 2 + par;
                    bv[q * 2 + par] = sb[col];
                    wv[q * 2 + par] = sw[col];
                }
            float ps[4] = {0.f, 0.f, 0.f, 0.f};
#pragma unroll
            for (int s = 0; s < 2; ++s)
#pragma unroll
                for (int q = 0; q < 8; ++q)
#pragma unroll
                    for (int e = 0; e < 4; ++e) {
                        float z = acc[s][q][e] + bv[q * 2 + (e & 1)];
                        ps[s * 2 + (e >> 1)] += tanh_approx(z) * wv[q * 2 + (e & 1)];
                    }
#pragma unroll
            for (int q = 0; q < 4; ++q) {
                ps[q] += __shfl_xor_sync(0xffffffffu, ps[q], 1);
                ps[q] += __shfl_xor_sync(0xffffffffu, ps[q], 2);
            }
            if ((lane & 3) == 0) {
#pragma unroll
                for (int q = 0; q < 4; ++q) {
                    int r = rb + (q >> 1) * 16 + (lane >> 2) + (q & 1) * 8;
                    se[wn * 128 + r] = ps[q];
                }
            }
            asm volatile("bar.sync 1, 256;" ::: "memory");

            // epilogue part 2: p = exp(e) (no max shift: |e| <= ||w||_1 ~ 9),
            // batch id per row
            if (tid < 128) {
                long grow = tj * TILE + tid;
                bool valid = grow < (long)V;
                float e = se[tid] + se[128 + tid];
                spool[tid] = valid ? __expf(e) : 0.f;
                int g = -1;
                if (valid)
                    g = is64 ? (int)((const long long*)bt)[grow]
                             : ((const int*)bt)[grow];
                sbat[tid] = g;
            }
            asm volatile("bar.sync 1, 256;" ::: "memory");
            if (tid < 128)
                sflag[tid] = (tid == 0) || (sbat[tid] != sbat[tid - 1]);
            asm volatile("bar.sync 1, 256;" ::: "memory");

            // epilogue part 3: segment-partial pooling from smem H (hi+lo)
            const __half* hhi = (const __half*)(smem + (b ? SM_A1HI : SM_A0HI));
            const __half* hlo = (const __half*)(smem + (b ? SM_A1LO : SM_A0LO));
            if (tid < 128) {
                int d = tid;
                float pacc = 0.f;
                int g = sbat[0];
                for (int r = 0; r < 128; ++r) {
                    if (r && sflag[r]) {
                        if (g >= 0)
                            atomicAdd(num + (size_t)g * D + d, pacc);
                        pacc = 0.f;
                        g = sbat[r];
                    }
                    float h = __half2float(hhi[r * AP + d]) +
                              __half2float(hlo[r * AP + d]);
                    pacc += spool[r] * h;
                }
                if (g >= 0) atomicAdd(num + (size_t)g * D + d, pacc);
            } else if (tid < 256) {
                int r0 = tid - 128;
                int g = sbat[r0];
                if (sflag[r0] && g >= 0) {
                    float s = 0.f;
                    for (int r = r0; r < 128 && sbat[r] == g; ++r)
                        s += spool[r];
                    atomicAdd(g_den + g, s);
                }
            }
        }
        __syncthreads();
    }
}

// ---------------- K_div: out = num / max(den, 1e-12) ----------------
__global__ void k_div(float* __restrict__ out, int n) {
    int i = blockIdx.x * 256 + threadIdx.x;
    if (i < n) out[i] = out[i] / fmaxf(g_den[i >> 7], 1e-12f);
}

// ---------------- launch ----------------
extern "C" void kernel_launch(void* const* d_in, const int* in_sizes, int n_in,
                              void* d_out, int out_size) {
    const float* H  = (const float*)d_in[0];
    const void*  bt = d_in[1];
    const float* Wp = (const float*)d_in[2];
    const float* bp = (const float*)d_in[3];
    const float* ws = (const float*)d_in[4];
    float* out = (float*)d_out;

    int V = in_sizes[1];
    int nTiles = (V + TILE - 1) / TILE;

    cudaFuncSetAttribute(k1_tc, cudaFuncAttributeMaxDynamicSharedMemorySize,
                         SMEM1_TOTAL);

    k_prep<<<(MAXG + 255) / 256, 256>>>(Wp, bt, V);
    k_zero<<<(out_size + 255) / 256, 256>>>(out, out_size);
    k1_tc<<<NSM, NTHR, SMEM1_TOTAL>>>(H, bt, bp, ws, out, V, nTiles);
    k_div<<<(out_size + 255) / 256, 256>>>(out, out_size);
}

// round 7
// speedup vs baseline: 1.1665x; 1.1310x over previous
#include <cuda_runtime.h>
#include <cuda_fp16.h>
#include <cstdint>

#define D    128
#define HS   128
#define MAXG 16384
#define AP   136      // padded smem row pitch in fp16 elems
#define TILE 128      // rows per tile
#define NSM  148
#define NTHR 384      // 8 consumer warps + 4 producer warps

// ---------------- device scratch ----------------
__device__ float g_den[MAXG];
__device__ int   g_is64;
__device__ __align__(16) __half g_Wh[HS * D];

// ---------------- smem layout (bytes) ----------------
#define SM_SB    0                       // 128 f32 bias
#define SM_SW    512                     // 128 f32 w_score
#define SM_SE    1024                    // 2 x 128 f32
#define SM_POOL  2048                    // 128 f32 exp(e)
#define SM_BAT   2560                    // 128 int batch ids
#define SM_BHI   3584                    // 128 x AP fp16 = 34816
#define SM_A0HI  (SM_BHI + 34816)        // 38400
#define SM_A0LO  (SM_A0HI + 34816)       // 73216
#define SM_A1HI  (SM_A0LO + 34816)       // 108032
#define SM_A1LO  (SM_A1HI + 34816)       // 142848
#define SMEM1_TOTAL (SM_A1LO + 34816)    // 177664

// ---------------- helpers ----------------
__device__ __forceinline__ unsigned su32(const void* p) {
    return (unsigned)__cvta_generic_to_shared(p);
}
__device__ __forceinline__ unsigned pkh(__half a, __half b) {
    unsigned short ua = *(unsigned short*)&a, ub = *(unsigned short*)&b;
    return (unsigned)ua | ((unsigned)ub << 16);
}
__device__ __forceinline__ float tanh_approx(float x) {
    float y;
    asm("tanh.approx.f32 %0, %1;" : "=f"(y) : "f"(x));
    return y;
}

#define LDSM4(r0, r1, r2, r3, addr)                                          \
    asm volatile("ldmatrix.sync.aligned.m8n8.x4.shared.b16 {%0,%1,%2,%3}, [%4];" \
                 : "=r"(r0), "=r"(r1), "=r"(r2), "=r"(r3) : "r"(addr))

#define MMA16816F(c, a0, a1, a2, a3, b0, b1)                                 \
    asm volatile(                                                            \
        "mma.sync.aligned.m16n8k16.row.col.f32.f16.f16.f32 "                 \
        "{%0,%1,%2,%3},{%4,%5,%6,%7},{%8,%9},{%0,%1,%2,%3};"                 \
        : "+f"(c[0]), "+f"(c[1]), "+f"(c[2]), "+f"(c[3])                     \
        : "r"(a0), "r"(a1), "r"(a2), "r"(a3), "r"(b0), "r"(b1))

// ---------------- K_prep: W -> fp16, zero den, batch dtype flag ----------
__global__ void k_prep(const float* __restrict__ W,
                       const void* __restrict__ bt, int V) {
    int i = blockIdx.x * 256 + threadIdx.x;
    if (i < HS * D) g_Wh[i] = __float2half_rn(W[i]);
    if (i < MAXG) g_den[i] = 0.f;
    if (i == 0)
        g_is64 = (((const unsigned long long*)bt)[V / 2 - 1] < (1ULL << 31)) ? 1 : 0;
}

__global__ void k_zero(float* __restrict__ out, int n) {
    int i = blockIdx.x * 256 + threadIdx.x;
    if (i < n) out[i] = 0.f;
}

// ---------------- K1 staging: TILE x 128 fp32 -> fp16 hi/lo ----------------
__device__ __forceinline__ void stage_tile(char* smem, const float* __restrict__ H,
                                           long tile, int buf, int V,
                                           int tpart, int npart) {
    __half* dhi = (__half*)(smem + (buf ? SM_A1HI : SM_A0HI));
    __half* dlo = (__half*)(smem + (buf ? SM_A1LO : SM_A0LO));
    for (int idx = tpart; idx < TILE * 16; idx += npart) {
        int row = idx >> 4;
        int k8  = (idx & 15) << 3;
        long gr = tile * TILE + row;
        float4 v0 = make_float4(0.f, 0.f, 0.f, 0.f), v1 = v0;
        if (gr < (long)V) {
            const float4* p = (const float4*)(H + (size_t)gr * D + k8);
            v0 = p[0];
            v1 = p[1];
        }
        float f[8] = {v0.x, v0.y, v0.z, v0.w, v1.x, v1.y, v1.z, v1.w};
        unsigned hi[4], lo[4];
#pragma unroll
        for (int p2 = 0; p2 < 4; ++p2) {
            __half ha = __float2half_rn(f[2 * p2]);
            __half hb = __float2half_rn(f[2 * p2 + 1]);
            __half la = __float2half_rn(f[2 * p2] - __half2float(ha));
            __half lb = __float2half_rn(f[2 * p2 + 1] - __half2float(hb));
            hi[p2] = pkh(ha, hb);
            lo[p2] = pkh(la, lb);
        }
        int off = row * AP + k8;
        *(uint4*)(dhi + off) = make_uint4(hi[0], hi[1], hi[2], hi[3]);
        *(uint4*)(dlo + off) = make_uint4(lo[0], lo[1], lo[2], lo[3]);
    }
}

// ---------------- K1: persistent 2-pass fp16 HMMA + fused softmax-pool ----
__global__ __launch_bounds__(NTHR, 1) void k1_tc(const float* __restrict__ H,
                                                 const void* __restrict__ bt,
                                                 const float* __restrict__ bp,
                                                 const float* __restrict__ ws,
                                                 float* __restrict__ num,
                                                 int V, int nTiles) {
    extern __shared__ __align__(16) char smem[];
    int tid = threadIdx.x, wid = tid >> 5, lane = tid & 31;
    float* sb    = (float*)(smem + SM_SB);
    float* sw    = (float*)(smem + SM_SW);
    float* se    = (float*)(smem + SM_SE);    // [2][128]
    float* spool = (float*)(smem + SM_POOL);  // [128]
    int*   sbat  = (int*)(smem + SM_BAT);     // [128]

    if (tid < 128) { sb[tid] = bp[tid]; sw[tid] = ws[tid]; }
    int is64 = g_is64;

    // stage stationary B = fp16(W)
    for (int idx = tid; idx < 128 * 16; idx += NTHR) {
        int row = idx >> 4;
        int k8  = (idx & 15) << 3;
        uint4 vh = *(const uint4*)(g_Wh + row * D + k8);
        *(uint4*)((__half*)(smem + SM_BHI) + row * AP + k8) = vh;
    }

    int nt = 0;
    {
        int rem = nTiles - blockIdx.x;
        if (rem > 0) nt = (rem + (int)gridDim.x - 1) / (int)gridDim.x;
    }

    if (nt > 0)
        stage_tile((char*)smem, H, (long)blockIdx.x, 0, V, tid, NTHR);
    __syncthreads();

    // consumer geometry (warps 0-7): 4(M) x 2(N), warp tile 32 x 64
    int wm = wid >> 1, wn = wid & 1;
    int rb = wm * 32, cb = wn * 64;
    unsigned aoff = ((rb + (lane & 15)) * AP + ((lane >> 4) << 3)) * 2;
    unsigned boff =
        ((cb + (lane & 7) + ((lane >> 4) << 3)) * AP + (((lane >> 3) & 1) << 3)) * 2;
    unsigned bhi_s = su32(smem + SM_BHI) + boff;

    for (int j = 0; j < nt; ++j) {
        int b = j & 1, bn = (j + 1) & 1;
        long tj = (long)blockIdx.x + (long)j * gridDim.x;

        if (wid >= 8) {
            // producers: stage next tile
            if (j + 1 < nt) {
                long tj1 = (long)blockIdx.x + (long)(j + 1) * gridDim.x;
                stage_tile((char*)smem, H, tj1, bn, V, tid - 256, 128);
            }
        } else {
            unsigned ahi_s = su32(smem + (b ? SM_A1HI : SM_A0HI)) + aoff;
            unsigned alo_s = su32(smem + (b ? SM_A1LO : SM_A0LO)) + aoff;

            float acc[2][8][4];
#pragma unroll
            for (int s = 0; s < 2; s++)
#pragma unroll
                for (int q = 0; q < 8; q++)
#pragma unroll
                    for (int c = 0; c < 4; c++) acc[s][q][c] = 0.f;

#pragma unroll
            for (int kk = 0; kk < 8; ++kk) {
                unsigned ah[2][4], bh[16];
#pragma unroll
                for (int s = 0; s < 2; ++s)
                    LDSM4(ah[s][0], ah[s][1], ah[s][2], ah[s][3],
                          ahi_s + kk * 32 + s * (16 * AP * 2));
#pragma unroll
                for (int p = 0; p < 4; ++p)
                    LDSM4(bh[4 * p], bh[4 * p + 1], bh[4 * p + 2], bh[4 * p + 3],
                          bhi_s + kk * 32 + p * (16 * AP * 2));
                // pass 0: Ahi * B
#pragma unroll
                for (int s = 0; s < 2; ++s)
#pragma unroll
                    for (int q = 0; q < 8; ++q) {
                        int bi = (q >> 1) * 4 + ((q & 1) << 1);
                        MMA16816F(acc[s][q], ah[s][0], ah[s][1], ah[s][2],
                                  ah[s][3], bh[bi], bh[bi + 1]);
                    }
                // pass 1: Alo * B
                unsigned al[2][4];
#pragma unroll
                for (int s = 0; s < 2; ++s)
                    LDSM4(al[s][0], al[s][1], al[s][2], al[s][3],
                          alo_s + kk * 32 + s * (16 * AP * 2));
#pragma unroll
                for (int s = 0; s < 2; ++s)
#pragma unroll
                    for (int q = 0; q < 8; ++q) {
                        int bi = (q >> 1) * 4 + ((q & 1) << 1);
                        MMA16816F(acc[s][q], al[s][0], al[s][1], al[s][2],
                                  al[s][3], bh[bi], bh[bi + 1]);
                    }
            }

            // epilogue part 1: tanh-dot -> se
            float bv[16], wv[16];
#pragma unroll
            for (int q = 0; q < 8; ++q)
#pragma unroll
                for (int par = 0; par < 2; ++par) {
                    int col = cb + q * 8 + (lane & 3) * 2 + par;
                    bv[q * 2 + par] = sb[col];
                    wv[q * 2 + par] = sw[col];
                }
            float ps[4] = {0.f, 0.f, 0.f, 0.f};
#pragma unroll
            for (int s = 0; s < 2; ++s)
#pragma unroll
                for (int q = 0; q < 8; ++q)
#pragma unroll
                    for (int e = 0; e < 4; ++e) {
                        float z = acc[s][q][e] + bv[q * 2 + (e & 1)];
                        ps[s * 2 + (e >> 1)] += tanh_approx(z) * wv[q * 2 + (e & 1)];
                    }
#pragma unroll
            for (int q = 0; q < 4; ++q) {
                ps[q] += __shfl_xor_sync(0xffffffffu, ps[q], 1);
                ps[q] += __shfl_xor_sync(0xffffffffu, ps[q], 2);
            }
            if ((lane & 3) == 0) {
#pragma unroll
                for (int q = 0; q < 4; ++q) {
                    int r = rb + (q >> 1) * 16 + (lane >> 2) + (q & 1) * 8;
                    se[wn * 128 + r] = ps[q];
                }
            }
            asm volatile("bar.sync 1, 256;" ::: "memory");

            // epilogue part 2: p = exp(e) (no max shift: |e| <= ||w||_1 ~ 9),
            // batch id per row
            if (tid < 128) {
                long grow = tj * TILE + tid;
                bool valid = grow < (long)V;
                float e = se[tid] + se[128 + tid];
                spool[tid] = valid ? __expf(e) : 0.f;
                int g = -1;
                if (valid)
                    g = is64 ? (int)((const long long*)bt)[grow]
                             : ((const int*)bt)[grow];
                sbat[tid] = g;
            }
            asm volatile("bar.sync 1, 256;" ::: "memory");

            // epilogue part 3: parallel segment pooling.
            // Warp w owns rows [16w, 16w+16); lane owns 4 d-cols.
            {
                const __half* hhi = (const __half*)(smem + (b ? SM_A1HI : SM_A0HI));
                const __half* hlo = (const __half*)(smem + (b ? SM_A1LO : SM_A0LO));
                int r0 = wid * 16;
                int d4 = lane * 4;
                float pacc0 = 0.f, pacc1 = 0.f, pacc2 = 0.f, pacc3 = 0.f;
                float psum = 0.f;
                int g = sbat[r0];
#pragma unroll
                for (int rr = 0; rr < 16; ++rr) {
                    int r = r0 + rr;
                    int gr = sbat[r];
                    if (gr != g) {
                        if (g >= 0) {
                            float* dst = num + (size_t)g * D + d4;
                            atomicAdd(dst + 0, pacc0);
                            atomicAdd(dst + 1, pacc1);
                            atomicAdd(dst + 2, pacc2);
                            atomicAdd(dst + 3, pacc3);
                            if (lane == 0) atomicAdd(g_den + g, psum);
                        }
                        pacc0 = pacc1 = pacc2 = pacc3 = 0.f;
                        psum = 0.f;
                        g = gr;
                    }
                    float p = spool[r];
                    uint2 vh = *(const uint2*)(hhi + r * AP + d4);
                    uint2 vl = *(const uint2*)(hlo + r * AP + d4);
                    __half2 h0 = *(__half2*)&vh.x, h1 = *(__half2*)&vh.y;
                    __half2 l0 = *(__half2*)&vl.x, l1 = *(__half2*)&vl.y;
                    float2 f0 = __half22float2(h0), f1 = __half22float2(h1);
                    float2 e0 = __half22float2(l0), e1 = __half22float2(l1);
                    pacc0 += p * (f0.x + e0.x);
                    pacc1 += p * (f0.y + e0.y);
                    pacc2 += p * (f1.x + e1.x);
                    pacc3 += p * (f1.y + e1.y);
                    psum += p;
                }
                if (g >= 0) {
                    float* dst = num + (size_t)g * D + d4;
                    atomicAdd(dst + 0, pacc0);
                    atomicAdd(dst + 1, pacc1);
                    atomicAdd(dst + 2, pacc2);
                    atomicAdd(dst + 3, pacc3);
                    if (lane == 0) atomicAdd(g_den + g, psum);
                }
            }
        }
        __syncthreads();
    }
}

// ---------------- K_div: out = num / max(den, 1e-12) ----------------
__global__ void k_div(float* __restrict__ out, int n) {
    int i = blockIdx.x * 256 + threadIdx.x;
    if (i < n) out[i] = out[i] / fmaxf(g_den[i >> 7], 1e-12f);
}

// ---------------- launch ----------------
extern "C" void kernel_launch(void* const* d_in, const int* in_sizes, int n_in,
                              void* d_out, int out_size) {
    const float* H  = (const float*)d_in[0];
    const void*  bt = d_in[1];
    const float* Wp = (const float*)d_in[2];
    const float* bp = (const float*)d_in[3];
    const float* ws = (const float*)d_in[4];
    float* out = (float*)d_out;

    int V = in_sizes[1];
    int nTiles = (V + TILE - 1) / TILE;

    cudaFuncSetAttribute(k1_tc, cudaFuncAttributeMaxDynamicSharedMemorySize,
                         SMEM1_TOTAL);

    k_prep<<<(MAXG + 255) / 256, 256>>>(Wp, bt, V);
    k_zero<<<(out_size + 255) / 256, 256>>>(out, out_size);
    k1_tc<<<NSM, NTHR, SMEM1_TOTAL>>>(H, bt, bp, ws, out, V, nTiles);
    k_div<<<(out_size + 255) / 256, 256>>>(out, out_size);
}

// round 8
// speedup vs baseline: 1.1895x; 1.0197x over previous
#include <cuda_runtime.h>
#include <cuda_fp16.h>
#include <cstdint>

#define D    128
#define HS   128
#define MAXG 16384
#define AP   136      // padded smem row pitch in fp16 elems
#define TILE 128      // rows per tile
#define NSM  148
#define NTHR 384      // 8 consumer warps + 4 producer warps

// ---------------- device scratch ----------------
__device__ float g_den[MAXG];
__device__ int   g_is64;
__device__ __align__(16) __half g_Wh[HS * D];

// ---------------- smem layout (bytes) ----------------
#define SM_SB    0                       // 128 f32 bias
#define SM_SW    512                     // 128 f32 w_score
#define SM_SE    1024                    // 2 x 128 f32
#define SM_POOL  2048                    // 128 f32 exp(e)
#define SM_BAT   2560                    // 128 int batch ids
#define SM_BHI   3584                    // 128 x AP fp16 = 34816
#define SM_A0HI  (SM_BHI + 34816)        // 38400
#define SM_A0LO  (SM_A0HI + 34816)       // 73216
#define SM_A1HI  (SM_A0LO + 34816)       // 108032
#define SM_A1LO  (SM_A1HI + 34816)       // 142848
#define SMEM1_TOTAL (SM_A1LO + 34816)    // 177664

// ---------------- helpers ----------------
__device__ __forceinline__ unsigned su32(const void* p) {
    return (unsigned)__cvta_generic_to_shared(p);
}
__device__ __forceinline__ unsigned pkh(__half a, __half b) {
    unsigned short ua = *(unsigned short*)&a, ub = *(unsigned short*)&b;
    return (unsigned)ua | ((unsigned)ub << 16);
}
__device__ __forceinline__ float tanh_approx(float x) {
    float y;
    asm("tanh.approx.f32 %0, %1;" : "=f"(y) : "f"(x));
    return y;
}

#define LDSM4(r0, r1, r2, r3, addr)                                          \
    asm volatile("ldmatrix.sync.aligned.m8n8.x4.shared.b16 {%0,%1,%2,%3}, [%4];" \
                 : "=r"(r0), "=r"(r1), "=r"(r2), "=r"(r3) : "r"(addr))

#define MMA16816F(c, a0, a1, a2, a3, b0, b1)                                 \
    asm volatile(                                                            \
        "mma.sync.aligned.m16n8k16.row.col.f32.f16.f16.f32 "                 \
        "{%0,%1,%2,%3},{%4,%5,%6,%7},{%8,%9},{%0,%1,%2,%3};"                 \
        : "+f"(c[0]), "+f"(c[1]), "+f"(c[2]), "+f"(c[3])                     \
        : "r"(a0), "r"(a1), "r"(a2), "r"(a3), "r"(b0), "r"(b1))

// ---------------- K_prep: W -> fp16, zero den, batch dtype flag ----------
__global__ void k_prep(const float* __restrict__ W,
                       const void* __restrict__ bt, int V) {
    int i = blockIdx.x * 256 + threadIdx.x;
    if (i < HS * D) g_Wh[i] = __float2half_rn(W[i]);
    if (i < MAXG) g_den[i] = 0.f;
    if (i == 0)
        g_is64 = (((const unsigned long long*)bt)[V / 2 - 1] < (1ULL << 31)) ? 1 : 0;
}

__global__ void k_zero(float* __restrict__ out, int n) {
    int i = blockIdx.x * 256 + threadIdx.x;
    if (i < n) out[i] = 0.f;
}

// ---------------- K1 staging: TILE x 128 fp32 -> fp16 hi/lo ----------------
// hi feeds the MMA; hi+lo reconstruct H to fp32 accuracy for the pooling.
__device__ __forceinline__ void stage_tile(char* smem, const float* __restrict__ H,
                                           long tile, int buf, int V,
                                           int tpart, int npart) {
    __half* dhi = (__half*)(smem + (buf ? SM_A1HI : SM_A0HI));
    __half* dlo = (__half*)(smem + (buf ? SM_A1LO : SM_A0LO));
    for (int idx = tpart; idx < TILE * 16; idx += npart) {
        int row = idx >> 4;
        int k8  = (idx & 15) << 3;
        long gr = tile * TILE + row;
        float4 v0 = make_float4(0.f, 0.f, 0.f, 0.f), v1 = v0;
        if (gr < (long)V) {
            const float4* p = (const float4*)(H + (size_t)gr * D + k8);
            v0 = p[0];
            v1 = p[1];
        }
        float f[8] = {v0.x, v0.y, v0.z, v0.w, v1.x, v1.y, v1.z, v1.w};
        unsigned hi[4], lo[4];
#pragma unroll
        for (int p2 = 0; p2 < 4; ++p2) {
            __half ha = __float2half_rn(f[2 * p2]);
            __half hb = __float2half_rn(f[2 * p2 + 1]);
            __half la = __float2half_rn(f[2 * p2] - __half2float(ha));
            __half lb = __float2half_rn(f[2 * p2 + 1] - __half2float(hb));
            hi[p2] = pkh(ha, hb);
            lo[p2] = pkh(la, lb);
        }
        int off = row * AP + k8;
        *(uint4*)(dhi + off) = make_uint4(hi[0], hi[1], hi[2], hi[3]);
        *(uint4*)(dlo + off) = make_uint4(lo[0], lo[1], lo[2], lo[3]);
    }
}

// ---------------- K1: persistent 1-pass fp16 HMMA + fused softmax-pool ----
__global__ __launch_bounds__(NTHR, 1) void k1_tc(const float* __restrict__ H,
                                                 const void* __restrict__ bt,
                                                 const float* __restrict__ bp,
                                                 const float* __restrict__ ws,
                                                 float* __restrict__ num,
                                                 int V, int nTiles) {
    extern __shared__ __align__(16) char smem[];
    int tid = threadIdx.x, wid = tid >> 5, lane = tid & 31;
    float* sb    = (float*)(smem + SM_SB);
    float* sw    = (float*)(smem + SM_SW);
    float* se    = (float*)(smem + SM_SE);    // [2][128]
    float* spool = (float*)(smem + SM_POOL);  // [128]
    int*   sbat  = (int*)(smem + SM_BAT);     // [128]

    if (tid < 128) { sb[tid] = bp[tid]; sw[tid] = ws[tid]; }
    int is64 = g_is64;

    // stage stationary B = fp16(W)
    for (int idx = tid; idx < 128 * 16; idx += NTHR) {
        int row = idx >> 4;
        int k8  = (idx & 15) << 3;
        uint4 vh = *(const uint4*)(g_Wh + row * D + k8);
        *(uint4*)((__half*)(smem + SM_BHI) + row * AP + k8) = vh;
    }

    int nt = 0;
    {
        int rem = nTiles - blockIdx.x;
        if (rem > 0) nt = (rem + (int)gridDim.x - 1) / (int)gridDim.x;
    }

    if (nt > 0)
        stage_tile((char*)smem, H, (long)blockIdx.x, 0, V, tid, NTHR);
    __syncthreads();

    // consumer geometry (warps 0-7): 4(M) x 2(N), warp tile 32 x 64
    int wm = wid >> 1, wn = wid & 1;
    int rb = wm * 32, cb = wn * 64;
    unsigned aoff = ((rb + (lane & 15)) * AP + ((lane >> 4) << 3)) * 2;
    unsigned boff =
        ((cb + (lane & 7) + ((lane >> 4) << 3)) * AP + (((lane >> 3) & 1) << 3)) * 2;
    unsigned bhi_s = su32(smem + SM_BHI) + boff;

    for (int j = 0; j < nt; ++j) {
        int b = j & 1, bn = (j + 1) & 1;
        long tj = (long)blockIdx.x + (long)j * gridDim.x;

        if (wid >= 8) {
            // producers: stage next tile
            if (j + 1 < nt) {
                long tj1 = (long)blockIdx.x + (long)(j + 1) * gridDim.x;
                stage_tile((char*)smem, H, tj1, bn, V, tid - 256, 128);
            }
        } else {
            unsigned ahi_s = su32(smem + (b ? SM_A1HI : SM_A0HI)) + aoff;

            float acc[2][8][4];
#pragma unroll
            for (int s = 0; s < 2; s++)
#pragma unroll
                for (int q = 0; q < 8; q++)
#pragma unroll
                    for (int c = 0; c < 4; c++) acc[s][q][c] = 0.f;

#pragma unroll
            for (int kk = 0; kk < 8; ++kk) {
                unsigned ah[2][4], bh[16];
#pragma unroll
                for (int s = 0; s < 2; ++s)
                    LDSM4(ah[s][0], ah[s][1], ah[s][2], ah[s][3],
                          ahi_s + kk * 32 + s * (16 * AP * 2));
#pragma unroll
                for (int p = 0; p < 4; ++p)
                    LDSM4(bh[4 * p], bh[4 * p + 1], bh[4 * p + 2], bh[4 * p + 3],
                          bhi_s + kk * 32 + p * (16 * AP * 2));
                // single pass: Ahi * B
#pragma unroll
                for (int s = 0; s < 2; ++s)
#pragma unroll
                    for (int q = 0; q < 8; ++q) {
                        int bi = (q >> 1) * 4 + ((q & 1) << 1);
                        MMA16816F(acc[s][q], ah[s][0], ah[s][1], ah[s][2],
                                  ah[s][3], bh[bi], bh[bi + 1]);
                    }
            }

            // epilogue part 1: tanh-dot -> se
            float bv[16], wv[16];
#pragma unroll
            for (int q = 0; q < 8; ++q)
#pragma unroll
                for (int par = 0; par < 2; ++par) {
                    int col = cb + q * 8 + (lane & 3) * 2 + par;
                    bv[q * 2 + par] = sb[col];
                    wv[q * 2 + par] = sw[col];
                }
            float ps[4] = {0.f, 0.f, 0.f, 0.f};
#pragma unroll
            for (int s = 0; s < 2; ++s)
#pragma unroll
                for (int q = 0; q < 8; ++q)
#pragma unroll
                    for (int e = 0; e < 4; ++e) {
                        float z = acc[s][q][e] + bv[q * 2 + (e & 1)];
                        ps[s * 2 + (e >> 1)] += tanh_approx(z) * wv[q * 2 + (e & 1)];
                    }
#pragma unroll
            for (int q = 0; q < 4; ++q) {
                ps[q] += __shfl_xor_sync(0xffffffffu, ps[q], 1);
                ps[q] += __shfl_xor_sync(0xffffffffu, ps[q], 2);
            }
            if ((lane & 3) == 0) {
#pragma unroll
                for (int q = 0; q < 4; ++q) {
                    int r = rb + (q >> 1) * 16 + (lane >> 2) + (q & 1) * 8;
                    se[wn * 128 + r] = ps[q];
                }
            }
            asm volatile("bar.sync 1, 256;" ::: "memory");

            // epilogue part 2: p = exp(e) (no max shift: |e| <= ||w||_1 ~ 9),
            // batch id per row
            if (tid < 128) {
                long grow = tj * TILE + tid;
                bool valid = grow < (long)V;
                float e = se[tid] + se[128 + tid];
                spool[tid] = valid ? __expf(e) : 0.f;
                int g = -1;
                if (valid)
                    g = is64 ? (int)((const long long*)bt)[grow]
                             : ((const int*)bt)[grow];
                sbat[tid] = g;
            }
            asm volatile("bar.sync 1, 256;" ::: "memory");

            // epilogue part 3: parallel segment pooling (hi+lo = fp32-accurate H).
            // Warp w owns rows [16w, 16w+16); lane owns 4 d-cols.
            {
                const __half* hhi = (const __half*)(smem + (b ? SM_A1HI : SM_A0HI));
                const __half* hlo = (const __half*)(smem + (b ? SM_A1LO : SM_A0LO));
                int r0 = wid * 16;
                int d4 = lane * 4;
                float pacc0 = 0.f, pacc1 = 0.f, pacc2 = 0.f, pacc3 = 0.f;
                float psum = 0.f;
                int g = sbat[r0];
#pragma unroll
                for (int rr = 0; rr < 16; ++rr) {
                    int r = r0 + rr;
                    int gr = sbat[r];
                    if (gr != g) {
                        if (g >= 0) {
                            float* dst = num + (size_t)g * D + d4;
                            atomicAdd(dst + 0, pacc0);
                            atomicAdd(dst + 1, pacc1);
                            atomicAdd(dst + 2, pacc2);
                            atomicAdd(dst + 3, pacc3);
                            if (lane == 0) atomicAdd(g_den + g, psum);
                        }
                        pacc0 = pacc1 = pacc2 = pacc3 = 0.f;
                        psum = 0.f;
                        g = gr;
                    }
                    float p = spool[r];
                    uint2 vh = *(const uint2*)(hhi + r * AP + d4);
                    uint2 vl = *(const uint2*)(hlo + r * AP + d4);
                    __half2 h0 = *(__half2*)&vh.x, h1 = *(__half2*)&vh.y;
                    __half2 l0 = *(__half2*)&vl.x, l1 = *(__half2*)&vl.y;
                    float2 f0 = __half22float2(h0), f1 = __half22float2(h1);
                    float2 e0 = __half22float2(l0), e1 = __half22float2(l1);
                    pacc0 += p * (f0.x + e0.x);
                    pacc1 += p * (f0.y + e0.y);
                    pacc2 += p * (f1.x + e1.x);
                    pacc3 += p * (f1.y + e1.y);
                    psum += p;
                }
                if (g >= 0) {
                    float* dst = num + (size_t)g * D + d4;
                    atomicAdd(dst + 0, pacc0);
                    atomicAdd(dst + 1, pacc1);
                    atomicAdd(dst + 2, pacc2);
                    atomicAdd(dst + 3, pacc3);
                    if (lane == 0) atomicAdd(g_den + g, psum);
                }
            }
        }
        __syncthreads();
    }
}

// ---------------- K_div: out = num / max(den, 1e-12) ----------------
__global__ void k_div(float* __restrict__ out, int n) {
    int i = blockIdx.x * 256 + threadIdx.x;
    if (i < n) out[i] = out[i] / fmaxf(g_den[i >> 7], 1e-12f);
}

// ---------------- launch ----------------
extern "C" void kernel_launch(void* const* d_in, const int* in_sizes, int n_in,
                              void* d_out, int out_size) {
    const float* H  = (const float*)d_in[0];
    const void*  bt = d_in[1];
    const float* Wp = (const float*)d_in[2];
    const float* bp = (const float*)d_in[3];
    const float* ws = (const float*)d_in[4];
    float* out = (float*)d_out;

    int V = in_sizes[1];
    int nTiles = (V + TILE - 1) / TILE;

    cudaFuncSetAttribute(k1_tc, cudaFuncAttributeMaxDynamicSharedMemorySize,
                         SMEM1_TOTAL);

    k_prep<<<(MAXG + 255) / 256, 256>>>(Wp, bt, V);
    k_zero<<<(out_size + 255) / 256, 256>>>(out, out_size);
    k1_tc<<<NSM, NTHR, SMEM1_TOTAL>>>(H, bt, bp, ws, out, V, nTiles);
    k_div<<<(out_size + 255) / 256, 256>>>(out, out_size);
}

// round 9
// speedup vs baseline: 1.9402x; 1.6311x over previous
#include <cuda_runtime.h>
#include <cuda_fp16.h>
#include <cstdint>

#define D    128
#define HS   128
#define MAXG 16384
#define AP   136      // padded smem row pitch in fp16 elems
#define TILE 128      // rows per tile
#define NSM  148
#define NTHR 384      // 8 consumer warps + 4 producer warps

// ---------------- device scratch ----------------
__device__ float g_den[MAXG];
__device__ int   g_is64;
__device__ __align__(16) __half g_Wh[HS * D];

// ---------------- smem layout (bytes) ----------------
#define SM_SB    0                       // 128 f32 bias
#define SM_SW    512                     // 128 f32 w_score
#define SM_SE    1024                    // 2 x 128 f32
#define SM_POOL  2048                    // 128 f32 exp(e)
#define SM_BAT0  2560                    // 128 int batch ids (buf 0)
#define SM_BAT1  3072                    // 128 int batch ids (buf 1)
#define SM_BHI   3584                    // 128 x AP fp16 = 34816
#define SM_A0    (SM_BHI + 34816)        // 38400
#define SM_A1    (SM_A0 + 34816)         // 73216
#define SMEM1_TOTAL (SM_A1 + 34816)      // 108032

// ---------------- helpers ----------------
__device__ __forceinline__ unsigned su32(const void* p) {
    return (unsigned)__cvta_generic_to_shared(p);
}
__device__ __forceinline__ float tanh_approx(float x) {
    float y;
    asm("tanh.approx.f32 %0, %1;" : "=f"(y) : "f"(x));
    return y;
}

#define LDSM4(r0, r1, r2, r3, addr)                                          \
    asm volatile("ldmatrix.sync.aligned.m8n8.x4.shared.b16 {%0,%1,%2,%3}, [%4];" \
                 : "=r"(r0), "=r"(r1), "=r"(r2), "=r"(r3) : "r"(addr))

#define MMA16816F(c, a0, a1, a2, a3, b0, b1)                                 \
    asm volatile(                                                            \
        "mma.sync.aligned.m16n8k16.row.col.f32.f16.f16.f32 "                 \
        "{%0,%1,%2,%3},{%4,%5,%6,%7},{%8,%9},{%0,%1,%2,%3};"                 \
        : "+f"(c[0]), "+f"(c[1]), "+f"(c[2]), "+f"(c[3])                     \
        : "r"(a0), "r"(a1), "r"(a2), "r"(a3), "r"(b0), "r"(b1))

// ---------------- K_prep: W -> fp16, zero den, batch dtype flag ----------
__global__ void k_prep(const float* __restrict__ W,
                       const void* __restrict__ bt, int V) {
    int i = blockIdx.x * 256 + threadIdx.x;
    if (i < HS * D) g_Wh[i] = __float2half_rn(W[i]);
    if (i < MAXG) g_den[i] = 0.f;
    if (i == 0)
        g_is64 = (((const unsigned long long*)bt)[V / 2 - 1] < (1ULL << 31)) ? 1 : 0;
}

__global__ void k_zero(float* __restrict__ out, int n) {
    int i = blockIdx.x * 256 + threadIdx.x;
    if (i < n) out[i] = 0.f;
}

// ---------------- K1 staging: TILE x 128 fp32 -> fp16 (packed cvt) --------
__device__ __forceinline__ void stage_tile(char* smem, const float* __restrict__ H,
                                           long tile, int buf, int V,
                                           int tpart, int npart) {
    __half* dst = (__half*)(smem + (buf ? SM_A1 : SM_A0));
    for (int idx = tpart; idx < TILE * 16; idx += npart) {
        int row = idx >> 4;
        int k8  = (idx & 15) << 3;
        long gr = tile * TILE + row;
        float4 v0 = make_float4(0.f, 0.f, 0.f, 0.f), v1 = v0;
        if (gr < (long)V) {
            const float4* p = (const float4*)(H + (size_t)gr * D + k8);
            v0 = p[0];
            v1 = p[1];
        }
        __half2 h0 = __float22half2_rn(make_float2(v0.x, v0.y));
        __half2 h1 = __float22half2_rn(make_float2(v0.z, v0.w));
        __half2 h2 = __float22half2_rn(make_float2(v1.x, v1.y));
        __half2 h3 = __float22half2_rn(make_float2(v1.z, v1.w));
        uint4 pack = make_uint4(*(unsigned*)&h0, *(unsigned*)&h1,
                                *(unsigned*)&h2, *(unsigned*)&h3);
        *(uint4*)(dst + row * AP + k8) = pack;
    }
}

// prefetch batch ids for a tile into a double-buffered smem array
__device__ __forceinline__ void stage_bat(char* smem, const void* __restrict__ bt,
                                          long tile, int buf, int V, int is64,
                                          int tpart) {
    // tpart in [0,128)
    int* dst = (int*)(smem + (buf ? SM_BAT1 : SM_BAT0));
    long gr = tile * TILE + tpart;
    int g = -1;
    if (gr < (long)V)
        g = is64 ? (int)((const long long*)bt)[gr] : ((const int*)bt)[gr];
    dst[tpart] = g;
}

// ---------------- K1: persistent fp16 HMMA + fused softmax-pool -----------
__global__ __launch_bounds__(NTHR, 1) void k1_tc(const float* __restrict__ H,
                                                 const void* __restrict__ bt,
                                                 const float* __restrict__ bp,
                                                 const float* __restrict__ ws,
                                                 float* __restrict__ num,
                                                 int V, int nTiles) {
    extern __shared__ __align__(16) char smem[];
    int tid = threadIdx.x, wid = tid >> 5, lane = tid & 31;
    float* sb    = (float*)(smem + SM_SB);
    float* sw    = (float*)(smem + SM_SW);
    float* se    = (float*)(smem + SM_SE);    // [2][128]
    float* spool = (float*)(smem + SM_POOL);  // [128]

    if (tid < 128) { sb[tid] = bp[tid]; sw[tid] = ws[tid]; }
    int is64 = g_is64;

    // stage stationary B = fp16(W)
    for (int idx = tid; idx < 128 * 16; idx += NTHR) {
        int row = idx >> 4;
        int k8  = (idx & 15) << 3;
        uint4 vh = *(const uint4*)(g_Wh + row * D + k8);
        *(uint4*)((__half*)(smem + SM_BHI) + row * AP + k8) = vh;
    }

    int nt = 0;
    {
        int rem = nTiles - blockIdx.x;
        if (rem > 0) nt = (rem + (int)gridDim.x - 1) / (int)gridDim.x;
    }

    if (nt > 0) {
        stage_tile((char*)smem, H, (long)blockIdx.x, 0, V, tid, NTHR);
        if (tid < 128)
            stage_bat((char*)smem, bt, (long)blockIdx.x, 0, V, is64, tid);
    }
    __syncthreads();

    // consumer geometry (warps 0-7): 4(M) x 2(N), warp tile 32 x 64
    int wm = wid >> 1, wn = wid & 1;
    int rb = wm * 32, cb = wn * 64;
    unsigned aoff = ((rb + (lane & 15)) * AP + ((lane >> 4) << 3)) * 2;
    unsigned boff =
        ((cb + (lane & 7) + ((lane >> 4) << 3)) * AP + (((lane >> 3) & 1) << 3)) * 2;
    unsigned bhi_s = su32(smem + SM_BHI) + boff;

    for (int j = 0; j < nt; ++j) {
        int b = j & 1, bn = (j + 1) & 1;
        long tj = (long)blockIdx.x + (long)j * gridDim.x;
        int* sbat = (int*)(smem + (b ? SM_BAT1 : SM_BAT0));

        if (wid >= 8) {
            // producers: stage next tile + next batch ids
            if (j + 1 < nt) {
                long tj1 = (long)blockIdx.x + (long)(j + 1) * gridDim.x;
                stage_tile((char*)smem, H, tj1, bn, V, tid - 256, 128);
                if (tid - 256 < 128)
                    stage_bat((char*)smem, bt, tj1, bn, V, is64, tid - 256);
            }
        } else {
            unsigned a_s = su32(smem + (b ? SM_A1 : SM_A0)) + aoff;

            float acc[2][8][4];
#pragma unroll
            for (int s = 0; s < 2; s++)
#pragma unroll
                for (int q = 0; q < 8; q++)
#pragma unroll
                    for (int c = 0; c < 4; c++) acc[s][q][c] = 0.f;

#pragma unroll
            for (int kk = 0; kk < 8; ++kk) {
                unsigned ah[2][4], bh[16];
#pragma unroll
                for (int s = 0; s < 2; ++s)
                    LDSM4(ah[s][0], ah[s][1], ah[s][2], ah[s][3],
                          a_s + kk * 32 + s * (16 * AP * 2));
#pragma unroll
                for (int p = 0; p < 4; ++p)
                    LDSM4(bh[4 * p], bh[4 * p + 1], bh[4 * p + 2], bh[4 * p + 3],
                          bhi_s + kk * 32 + p * (16 * AP * 2));
#pragma unroll
                for (int s = 0; s < 2; ++s)
#pragma unroll
                    for (int q = 0; q < 8; ++q) {
                        int bi = (q >> 1) * 4 + ((q & 1) << 1);
                        MMA16816F(acc[s][q], ah[s][0], ah[s][1], ah[s][2],
                                  ah[s][3], bh[bi], bh[bi + 1]);
                    }
            }

            // epilogue part 1: tanh-dot -> se
            float bv[16], wv[16];
#pragma unroll
            for (int q = 0; q < 8; ++q)
#pragma unroll
                for (int par = 0; par < 2; ++par) {
                    int col = cb + q * 8 + (lane & 3) * 2 + par;
                    bv[q * 2 + par] = sb[col];
                    wv[q * 2 + par] = sw[col];
                }
            float ps[4] = {0.f, 0.f, 0.f, 0.f};
#pragma unroll
            for (int s = 0; s < 2; ++s)
#pragma unroll
                for (int q = 0; q < 8; ++q)
#pragma unroll
                    for (int e = 0; e < 4; ++e) {
                        float z = acc[s][q][e] + bv[q * 2 + (e & 1)];
                        ps[s * 2 + (e >> 1)] += tanh_approx(z) * wv[q * 2 + (e & 1)];
                    }
#pragma unroll
            for (int q = 0; q < 4; ++q) {
                ps[q] += __shfl_xor_sync(0xffffffffu, ps[q], 1);
                ps[q] += __shfl_xor_sync(0xffffffffu, ps[q], 2);
            }
            if ((lane & 3) == 0) {
#pragma unroll
                for (int q = 0; q < 4; ++q) {
                    int r = rb + (q >> 1) * 16 + (lane >> 2) + (q & 1) * 8;
                    se[wn * 128 + r] = ps[q];
                }
            }
            asm volatile("bar.sync 1, 256;" ::: "memory");

            // epilogue part 2: p = exp(e) (no max shift: |e| <= ||w||_1 ~ 9)
            if (tid < 128) {
                long grow = tj * TILE + tid;
                float e = se[tid] + se[128 + tid];
                spool[tid] = (grow < (long)V) ? __expf(e) : 0.f;
            }
            asm volatile("bar.sync 1, 256;" ::: "memory");

            // epilogue part 3: parallel segment pooling from fp16 H tile.
            // Warp w owns rows [16w, 16w+16); lane owns 4 d-cols.
            {
                const __half* hh = (const __half*)(smem + (b ? SM_A1 : SM_A0));
                int r0 = wid * 16;
                int d4 = lane * 4;
                float pacc0 = 0.f, pacc1 = 0.f, pacc2 = 0.f, pacc3 = 0.f;
                float psum = 0.f;
                int g = sbat[r0];
#pragma unroll
                for (int rr = 0; rr < 16; ++rr) {
                    int r = r0 + rr;
                    int gr = sbat[r];
                    if (gr != g) {
                        if (g >= 0) {
                            float* dst = num + (size_t)g * D + d4;
                            atomicAdd(dst + 0, pacc0);
                            atomicAdd(dst + 1, pacc1);
                            atomicAdd(dst + 2, pacc2);
                            atomicAdd(dst + 3, pacc3);
                            if (lane == 0) atomicAdd(g_den + g, psum);
                        }
                        pacc0 = pacc1 = pacc2 = pacc3 = 0.f;
                        psum = 0.f;
                        g = gr;
                    }
                    float p = spool[r];
                    uint2 vh = *(const uint2*)(hh + r * AP + d4);
                    __half2 h0 = *(__half2*)&vh.x, h1 = *(__half2*)&vh.y;
                    float2 f0 = __half22float2(h0), f1 = __half22float2(h1);
                    pacc0 += p * f0.x;
                    pacc1 += p * f0.y;
                    pacc2 += p * f1.x;
                    pacc3 += p * f1.y;
                    psum += p;
                }
                if (g >= 0) {
                    float* dst = num + (size_t)g * D + d4;
                    atomicAdd(dst + 0, pacc0);
                    atomicAdd(dst + 1, pacc1);
                    atomicAdd(dst + 2, pacc2);
                    atomicAdd(dst + 3, pacc3);
                    if (lane == 0) atomicAdd(g_den + g, psum);
                }
            }
        }
        __syncthreads();
    }
}

// ---------------- K_div: out = num / max(den, 1e-12) ----------------
__global__ void k_div(float* __restrict__ out, int n) {
    int i = blockIdx.x * 256 + threadIdx.x;
    if (i < n) out[i] = out[i] / fmaxf(g_den[i >> 7], 1e-12f);
}

// ---------------- launch ----------------
extern "C" void kernel_launch(void* const* d_in, const int* in_sizes, int n_in,
                              void* d_out, int out_size) {
    const float* H  = (const float*)d_in[0];
    const void*  bt = d_in[1];
    const float* Wp = (const float*)d_in[2];
    const float* bp = (const float*)d_in[3];
    const float* ws = (const float*)d_in[4];
    float* out = (float*)d_out;

    int V = in_sizes[1];
    int nTiles = (V + TILE - 1) / TILE;

    cudaFuncSetAttribute(k1_tc, cudaFuncAttributeMaxDynamicSharedMemorySize,
                         SMEM1_TOTAL);

    k_prep<<<(MAXG + 255) / 256, 256>>>(Wp, bt, V);
    k_zero<<<(out_size + 255) / 256, 256>>>(out, out_size);
    k1_tc<<<NSM, NTHR, SMEM1_TOTAL>>>(H, bt, bp, ws, out, V, nTiles);
    k_div<<<(out_size + 255) / 256, 256>>>(out, out_size);
}